// round 4
// baseline (speedup 1.0000x reference)
#include <cuda_runtime.h>

#define C     10
#define C2    20
#define HW    128
#define TW    16
#define TH    16
#define HALOW 18
#define HALOH 18
#define HS    (HALOW*HALOH)   // 324
#define NTHR  128

typedef unsigned long long ull;

// ---- global weight scratch (pre-folded by setup kernel) ----
// [0:3600)     wrel dup {wf,wf,wh,wh} per (ci*9+k)*10+co, BN-folded
// [3600:4400)  gates_w dup {w1,w1,w2,w2} per (co*10+ci), co in [0,20)
// [4400:4800)  can_w   dup {w1,w1,w2,w2} per (co*10+ci), co in [0,10)
// [4800:4810)  bn folded bias b2[co]
// [4810:4830)  gates_b
// [4830:4840)  can_b
// [4840:4860)  att_w
// [4860]       att_b
#define GW_WG   3600
#define GW_WC   4400
#define GW_B2   4800
#define GW_GB   4810
#define GW_CB   4830
#define GW_ATTW 4840
#define GW_ATTB 4860
__device__ float g_wbuf[4864];

// smem: tiles (3*C*HS = 9720 floats) + wrel dup (3600 floats) = 13320 floats
#define OFF_F     0
#define OFF_H0    (C*HS)
#define OFF_H1    (2*C*HS)
#define OFF_WREL  (3*C*HS)
#define SMEM_FLOATS (OFF_WREL + C*9*C*4)
#define SMEM_BYTES  (SMEM_FLOATS*4)       // 53280 B

__device__ __forceinline__ float fsigmoid(float x) { return 1.0f / (1.0f + __expf(-x)); }
__device__ __forceinline__ float ftanh_fast(float x) { return 1.0f - 2.0f / (__expf(2.0f * x) + 1.0f); }

__device__ __forceinline__ ull pack2(float lo, float hi) {
    ull r; asm("mov.b64 %0, {%1,%2};" : "=l"(r) : "f"(lo), "f"(hi)); return r;
}
__device__ __forceinline__ void unpack2(ull v, float& lo, float& hi) {
    asm("mov.b64 {%0,%1}, %2;" : "=f"(lo), "=f"(hi) : "l"(v));
}
__device__ __forceinline__ void fma2(ull& acc, ull a, ull b) {
    asm("fma.rn.f32x2 %0, %1, %2, %0;" : "+l"(acc) : "l"(a), "l"(b));
}
__device__ __forceinline__ ull mul2(ull a, ull b) {
    ull r; asm("mul.rn.f32x2 %0, %1, %2;" : "=l"(r) : "l"(a), "l"(b)); return r;
}

// ---------------- setup kernel: fold + duplicate weights ----------------
__global__ void setup_weights(const float* __restrict__ rel_w,
                              const float* __restrict__ bn_gamma,
                              const float* __restrict__ bn_beta,
                              const float* __restrict__ bn_mean,
                              const float* __restrict__ bn_var,
                              const float* __restrict__ gates_w,
                              const float* __restrict__ gates_b,
                              const float* __restrict__ can_w,
                              const float* __restrict__ can_b,
                              const float* __restrict__ att_w,
                              const float* __restrict__ att_b)
{
    const int tid = threadIdx.x;
    for (int e = tid; e < C*9*C; e += 256) {
        int co = e % C;
        int k  = (e / C) % 9;
        int ci = e / (9*C);
        float inv = bn_gamma[co] * rsqrtf(bn_var[co] + 1e-5f);
        float wf = rel_w[(co*C2 + ci)*9 + k] * inv;
        float wh = rel_w[(co*C2 + C + ci)*9 + k] * inv;
        float* d = g_wbuf + ((ci*9 + k)*C + co)*4;
        d[0] = wf; d[1] = wf; d[2] = wh; d[3] = wh;
    }
    for (int e = tid; e < C2*C; e += 256) {        // 200 gate entries
        int co = e / C, ci = e % C;
        float w1 = gates_w[co*C2 + ci];
        float w2 = gates_w[co*C2 + C + ci];
        float* d = g_wbuf + GW_WG + e*4;
        d[0] = w1; d[1] = w1; d[2] = w2; d[3] = w2;
    }
    for (int e = tid; e < C*C; e += 256) {          // 100 candidate entries
        int co = e / C, ci = e % C;
        float w1 = can_w[co*C2 + ci];
        float w2 = can_w[co*C2 + C + ci];
        float* d = g_wbuf + GW_WC + e*4;
        d[0] = w1; d[1] = w1; d[2] = w2; d[3] = w2;
    }
    if (tid < C) {
        float inv = bn_gamma[tid] * rsqrtf(bn_var[tid] + 1e-5f);
        g_wbuf[GW_B2 + tid] = bn_beta[tid] - bn_mean[tid] * inv;
        g_wbuf[GW_CB + tid] = can_b[tid];
    }
    if (tid < C2) {
        g_wbuf[GW_GB + tid]   = gates_b[tid];
        g_wbuf[GW_ATTW + tid] = att_w[tid];
    }
    if (tid == 0) g_wbuf[GW_ATTB] = att_b[0];
}

// ---------------- main fused kernel ----------------
__global__ void __launch_bounds__(NTHR, 4)
fused_tree_gru(const float* __restrict__ f_node,
               const float* __restrict__ h0g,
               const float* __restrict__ h1g,
               float* __restrict__ out_f,
               float* __restrict__ out_att)
{
    extern __shared__ float sm[];
    float* f_s   = sm + OFF_F;
    float* h0_s  = sm + OFF_H0;
    float* h1_s  = sm + OFF_H1;
    float* wrel2 = sm + OFF_WREL;

    const int tid = threadIdx.x;
    const int b   = blockIdx.z;
    const int tx0 = blockIdx.x * TW;
    const int ty0 = blockIdx.y * TH;

    // ---- stage folded conv weights (float4 copy) ----
    {
        const float4* src = reinterpret_cast<const float4*>(g_wbuf);
        float4* dst = reinterpret_cast<float4*>(wrel2);
        #pragma unroll
        for (int i = tid; i < C*9*C; i += NTHR) dst[i] = __ldg(src + i);
    }

    // ---- load haloed tiles (index math once per pixel) ----
    for (int p = tid; p < HS; p += NTHR) {
        int ly = p / HALOW, lx = p - ly*HALOW;
        int gy = ty0 - 1 + ly, gx = tx0 - 1 + lx;
        bool ok = (gy >= 0) & (gy < HW) & (gx >= 0) & (gx < HW);
        long gbase = ((long)(b*C)*HW + gy)*HW + gx;
        #pragma unroll
        for (int ci = 0; ci < C; ++ci) {
            long gi = gbase + (long)ci*HW*HW;
            int  si = ci*HS + p;
            f_s [si] = ok ? __ldg(f_node + gi) : 0.f;
            h0_s[si] = ok ? __ldg(h0g + gi)    : 0.f;
            h1_s[si] = ok ? __ldg(h1g + gi)    : 0.f;
        }
    }
    __syncthreads();

    // ---- attention: scale h tiles in place; write comp_att at center ----
    {
        float ab = __ldg(g_wbuf + GW_ATTB);
        for (int p = tid; p < HS; p += NTHR) {
            float v0[C], v1[C];
            float s = ab;
            #pragma unroll
            for (int ci = 0; ci < C; ++ci) {
                v0[ci] = h0_s[ci*HS + p];
                v1[ci] = h1_s[ci*HS + p];
                s += __ldg(g_wbuf + GW_ATTW + ci)*v0[ci]
                   + __ldg(g_wbuf + GW_ATTW + C + ci)*v1[ci];
            }
            float a = fsigmoid(s);
            #pragma unroll
            for (int ci = 0; ci < C; ++ci) {
                h0_s[ci*HS + p] = v0[ci]*a;
                h1_s[ci*HS + p] = v1[ci]*a;
            }
            int ly = p / HALOW, lx = p - ly*HALOW;
            if (ly >= 1 && ly <= TH && lx >= 1 && lx <= TW)
                out_att[((long)b*HW + (ty0 + ly - 1))*HW + (tx0 + lx - 1)] = a;
        }
    }
    __syncthreads();

    // ---- 3x3 conv, 2 pixels/thread via f32x2 ----
    const int txp  = (tid & 7) * 2;   // 0..14
    const int ty   = tid >> 3;        // 0..15
    const int base = ty*HALOW + txp;

    ull accf[C], acc0[C], acc1[C];
    #pragma unroll
    for (int co = 0; co < C; ++co) { accf[co] = 0ull; acc0[co] = 0ull; acc1[co] = 0ull; }

    for (int ci = 0; ci < C; ++ci) {
        const float* fb  = f_s  + ci*HS + base;
        const float* h0b = h0_s + ci*HS + base;
        const float* h1b = h1_s + ci*HS + base;
        const ulonglong2* wci = reinterpret_cast<const ulonglong2*>(wrel2 + ci*9*C*4);
        #pragma unroll
        for (int r = 0; r < 3; ++r) {
            const int ro = r*HALOW;
            float f0 = fb[ro],  f1 = fb[ro+1],  f2 = fb[ro+2],  f3 = fb[ro+3];
            float g0 = h0b[ro], g1 = h0b[ro+1], g2 = h0b[ro+2], g3 = h0b[ro+3];
            float e0 = h1b[ro], e1 = h1b[ro+1], e2 = h1b[ro+2], e3 = h1b[ro+3];
            ull fp[3] = { pack2(f0,f1), pack2(f1,f2), pack2(f2,f3) };
            ull p0[3] = { pack2(g0,g1), pack2(g1,g2), pack2(g2,g3) };
            ull p1[3] = { pack2(e0,e1), pack2(e1,e2), pack2(e2,e3) };
            #pragma unroll
            for (int kx = 0; kx < 3; ++kx) {
                const ulonglong2* wk = wci + (r*3 + kx)*C;
                ull fv = fp[kx], v0 = p0[kx], v1 = p1[kx];
                #pragma unroll
                for (int co = 0; co < C; ++co) {
                    ulonglong2 w = wk[co];
                    fma2(accf[co], w.x, fv);
                    fma2(acc0[co], w.y, v0);
                    fma2(acc1[co], w.y, v1);
                }
            }
        }
    }

    // ---- epilogue: BN bias + ReLU + sum -> packed comp_h / f center ----
    ull ch01[C], fc01[C];
    #pragma unroll
    for (int co = 0; co < C; ++co) {
        float cf0, cf1, x00, x01, x10, x11;
        unpack2(accf[co], cf0, cf1);
        unpack2(acc0[co], x00, x01);
        unpack2(acc1[co], x10, x11);
        float bz = __ldg(g_wbuf + GW_B2 + co);
        float c0 = fmaxf(cf0 + x00 + bz, 0.f) + fmaxf(cf0 + x10 + bz, 0.f);
        float c1 = fmaxf(cf1 + x01 + bz, 0.f) + fmaxf(cf1 + x11 + bz, 0.f);
        ch01[co] = pack2(c0, c1);
    }
    #pragma unroll
    for (int ci = 0; ci < C; ++ci) {
        const float* fc = f_s + ci*HS + (ty + 1)*HALOW + (txp + 1);
        fc01[ci] = pack2(fc[0], fc[1]);
    }

    // ---- ConvGRU gates (1x1), packed f32x2 ----
    ull r01[C], u01[C];
    #pragma unroll
    for (int co = 0; co < C2; ++co) {
        float gb = __ldg(g_wbuf + GW_GB + co);
        ull g = pack2(gb, gb);
        const ulonglong2* w = reinterpret_cast<const ulonglong2*>(g_wbuf + GW_WG) + co*C;
        #pragma unroll
        for (int ci = 0; ci < C; ++ci) {
            ulonglong2 ww = __ldg(w + ci);
            fma2(g, ww.x, ch01[ci]);
            fma2(g, ww.y, fc01[ci]);
        }
        float gg0, gg1; unpack2(g, gg0, gg1);
        ull s = pack2(fsigmoid(gg0), fsigmoid(gg1));
        if (co < C) r01[co] = s; else u01[co - C] = s;
    }
    ull rf01[C];
    #pragma unroll
    for (int ci = 0; ci < C; ++ci) rf01[ci] = mul2(r01[ci], fc01[ci]);

    // ---- candidate + update, write output ----
    const int gy = ty0 + ty, gx = tx0 + txp;
    #pragma unroll
    for (int co = 0; co < C; ++co) {
        float cb = __ldg(g_wbuf + GW_CB + co);
        ull g = pack2(cb, cb);
        const ulonglong2* w = reinterpret_cast<const ulonglong2*>(g_wbuf + GW_WC) + co*C;
        #pragma unroll
        for (int ci = 0; ci < C; ++ci) {
            ulonglong2 ww = __ldg(w + ci);
            fma2(g, ww.x, ch01[ci]);
            fma2(g, ww.y, rf01[ci]);
        }
        float gg0, gg1; unpack2(g, gg0, gg1);
        float t0 = ftanh_fast(gg0), t1 = ftanh_fast(gg1);
        float fc0, fc1; unpack2(fc01[co], fc0, fc1);
        float u0, u1;  unpack2(u01[co], u0, u1);
        float r0 = fc0 + u0*(t0 - fc0);
        float r1 = fc1 + u1*(t1 - fc1);
        long o = ((long)(b*C + co)*HW + gy)*HW + gx;
        *reinterpret_cast<float2*>(out_f + o) = make_float2(r0, r1);
    }
}

extern "C" void kernel_launch(void* const* d_in, const int* in_sizes, int n_in,
                              void* d_out, int out_size) {
    (void)n_in; (void)out_size;
    const float* f_node   = (const float*)d_in[0];
    const float* h0       = (const float*)d_in[1];
    const float* h1       = (const float*)d_in[2];
    // d_in[3] = p_nodes (unused), d_in[4] = xf (unused)
    const float* att_w    = (const float*)d_in[5];
    const float* att_b    = (const float*)d_in[6];
    const float* rel_w    = (const float*)d_in[7];
    const float* bn_gamma = (const float*)d_in[8];
    const float* bn_beta  = (const float*)d_in[9];
    const float* bn_mean  = (const float*)d_in[10];
    const float* bn_var   = (const float*)d_in[11];
    const float* gates_w  = (const float*)d_in[12];
    const float* gates_b  = (const float*)d_in[13];
    const float* can_w    = (const float*)d_in[14];
    const float* can_b    = (const float*)d_in[15];

    int B = in_sizes[0] / (C * HW * HW);
    float* out_f   = (float*)d_out;
    float* out_att = out_f + (long)B * C * HW * HW;

    static bool attr_set = false;
    if (!attr_set) {
        cudaFuncSetAttribute(fused_tree_gru,
                             cudaFuncAttributeMaxDynamicSharedMemorySize, SMEM_BYTES);
        cudaFuncSetAttribute(fused_tree_gru,
                             cudaFuncAttributePreferredSharedMemoryCarveout, 100);
        attr_set = true;
    }

    setup_weights<<<1, 256>>>(rel_w, bn_gamma, bn_beta, bn_mean, bn_var,
                              gates_w, gates_b, can_w, can_b, att_w, att_b);

    dim3 grid(HW / TW, HW / TH, B);
    fused_tree_gru<<<grid, NTHR, SMEM_BYTES>>>(f_node, h0, h1, out_f, out_att);
}

// round 5
// speedup vs baseline: 1.3782x; 1.3782x over previous
#include <cuda_runtime.h>

#define C     10
#define C2    20
#define HW    128
#define TW    32
#define TH    16
#define PITCH 35            // odd pitch -> conflict-free half-warp offsets
#define HALOH 18
#define HS    (PITCH*HALOH) // 630
#define NTHR  256

typedef unsigned long long ull;

// shared layout (floats)
#define OFF_F     0
#define OFF_H0    (C*HS)                    // 6300
#define OFF_H1    (2*C*HS)                  // 12600
#define OFF_WREL  (3*C*HS)                  // 18900 (x4 = 75600B, 16B aligned)
#define OFF_WG2   (OFF_WREL + C*9*C*4)      // 22500
#define OFF_WC2   (OFF_WG2 + C2*C*4)        // 23300
#define OFF_ATTW  (OFF_WC2 + C*C*4)         // 23700
#define OFF_GB    (OFF_ATTW + C2)           // 23720
#define OFF_CB    (OFF_GB + C2)             // 23740
#define OFF_B2    (OFF_CB + C)              // 23750
#define OFF_ATTB  (OFF_B2 + C)              // 23760
#define SMEM_FLOATS (OFF_ATTB + 1)
#define SMEM_BYTES (SMEM_FLOATS*4)          // ~95 KB

__device__ __forceinline__ float fsigmoid(float x) { return 1.0f / (1.0f + __expf(-x)); }
__device__ __forceinline__ float ftanh_fast(float x) { return 1.0f - 2.0f / (__expf(2.0f * x) + 1.0f); }

__device__ __forceinline__ ull pack2(float lo, float hi) {
    ull r; asm("mov.b64 %0, {%1,%2};" : "=l"(r) : "f"(lo), "f"(hi)); return r;
}
__device__ __forceinline__ void unpack2(ull v, float& lo, float& hi) {
    asm("mov.b64 {%0,%1}, %2;" : "=f"(lo), "=f"(hi) : "l"(v));
}
__device__ __forceinline__ void fma2(ull& acc, ull a, ull b) {
    asm("fma.rn.f32x2 %0, %1, %2, %0;" : "+l"(acc) : "l"(a), "l"(b));
}
__device__ __forceinline__ ull mul2(ull a, ull b) {
    ull r; asm("mul.rn.f32x2 %0, %1, %2;" : "=l"(r) : "l"(a), "l"(b)); return r;
}

__global__ void __launch_bounds__(NTHR, 2)
fused_tree_gru(const float* __restrict__ f_node,
               const float* __restrict__ h0g,
               const float* __restrict__ h1g,
               const float* __restrict__ att_w,
               const float* __restrict__ att_b,
               const float* __restrict__ rel_w,
               const float* __restrict__ bn_gamma,
               const float* __restrict__ bn_beta,
               const float* __restrict__ bn_mean,
               const float* __restrict__ bn_var,
               const float* __restrict__ gates_w,
               const float* __restrict__ gates_b,
               const float* __restrict__ can_w,
               const float* __restrict__ can_b,
               float* __restrict__ out_f,
               float* __restrict__ out_att)
{
    extern __shared__ float sm[];
    float* f_s    = sm + OFF_F;
    float* h0_s   = sm + OFF_H0;
    float* h1_s   = sm + OFF_H1;
    float* wrel2  = sm + OFF_WREL;   // {wf,wf,wh,wh} per (ci*9+k)*10+co, BN-folded
    float* wg2    = sm + OFF_WG2;    // {w1,w1,w2,w2} per co*10+ci, co in [0,20)
    float* wc2    = sm + OFF_WC2;    // {w1,w1,w2,w2} per co*10+ci, co in [0,10)
    float* attw_s = sm + OFF_ATTW;
    float* gb_s   = sm + OFF_GB;
    float* cb_s   = sm + OFF_CB;
    float* b2_s   = sm + OFF_B2;
    float* attb_s = sm + OFF_ATTB;

    const int tid = threadIdx.x;
    const int b   = blockIdx.z;
    const int tx0 = blockIdx.x * TW;
    const int ty0 = blockIdx.y * TH;

    // ---- stage weights (folded + duplicated) ----
    for (int e = tid; e < C*9*C; e += NTHR) {
        int co = e % C;
        int k  = (e / C) % 9;
        int ci = e / (9*C);
        float inv = bn_gamma[co] * rsqrtf(bn_var[co] + 1e-5f);
        float wf = rel_w[(co*C2 + ci)*9 + k] * inv;
        float wh = rel_w[(co*C2 + C + ci)*9 + k] * inv;
        float* d = wrel2 + e*4;
        d[0] = wf; d[1] = wf; d[2] = wh; d[3] = wh;
    }
    for (int e = tid; e < C2*C; e += NTHR) {
        int co = e / C, ci = e % C;
        float w1 = gates_w[co*C2 + ci];
        float w2 = gates_w[co*C2 + C + ci];
        float* d = wg2 + e*4;
        d[0] = w1; d[1] = w1; d[2] = w2; d[3] = w2;
    }
    if (tid < C*C) {
        int co = tid / C, ci = tid % C;
        float w1 = can_w[co*C2 + ci];
        float w2 = can_w[co*C2 + C + ci];
        float* d = wc2 + tid*4;
        d[0] = w1; d[1] = w1; d[2] = w2; d[3] = w2;
    }
    if (tid < C2) { attw_s[tid] = att_w[tid]; gb_s[tid] = gates_b[tid]; }
    if (tid < C) {
        cb_s[tid] = can_b[tid];
        float inv = bn_gamma[tid] * rsqrtf(bn_var[tid] + 1e-5f);
        b2_s[tid] = bn_beta[tid] - bn_mean[tid] * inv;
    }
    if (tid == 0) attb_s[0] = att_b[0];

    // ---- load haloed tiles (zero-pad; index math once per pixel) ----
    for (int p = tid; p < HS; p += NTHR) {
        int ly = p / PITCH, lx = p - ly*PITCH;
        int gy = ty0 - 1 + ly, gx = tx0 - 1 + lx;
        bool ok = (gy >= 0) & (gy < HW) & (gx >= 0) & (gx < HW) & (lx < TW + 2);
        long gbase = ((long)(b*C)*HW + gy)*HW + gx;
        #pragma unroll
        for (int ci = 0; ci < C; ++ci) {
            long gi = gbase + (long)ci*HW*HW;
            int  si = ci*HS + p;
            f_s [si] = ok ? f_node[gi] : 0.f;
            h0_s[si] = ok ? h0g[gi]    : 0.f;
            h1_s[si] = ok ? h1g[gi]    : 0.f;
        }
    }
    __syncthreads();

    // ---- attention: scale h tiles in place; write comp_att at center ----
    {
        float ab = attb_s[0];
        for (int p = tid; p < HS; p += NTHR) {
            float v0[C], v1[C];
            float s = ab;
            #pragma unroll
            for (int ci = 0; ci < C; ++ci) {
                v0[ci] = h0_s[ci*HS + p];
                v1[ci] = h1_s[ci*HS + p];
                s += attw_s[ci]*v0[ci] + attw_s[C+ci]*v1[ci];
            }
            float a = fsigmoid(s);
            #pragma unroll
            for (int ci = 0; ci < C; ++ci) {
                h0_s[ci*HS + p] = v0[ci]*a;
                h1_s[ci*HS + p] = v1[ci]*a;
            }
            int ly = p / PITCH, lx = p - ly*PITCH;
            if (ly >= 1 && ly <= TH && lx >= 1 && lx <= TW)
                out_att[((long)b*HW + (ty0 + ly - 1))*HW + (tx0 + lx - 1)] = a;
        }
    }
    __syncthreads();

    // ---- 3x3 conv, 2 pixels/thread via f32x2, conflict-free odd pitch ----
    const int txp  = (tid & 15) * 2;   // 0..30
    const int ty   = tid >> 4;         // 0..15
    const int base = ty*PITCH + txp;

    ull accf[C], acc0[C], acc1[C];
    #pragma unroll
    for (int co = 0; co < C; ++co) { accf[co] = 0ull; acc0[co] = 0ull; acc1[co] = 0ull; }

    for (int ci = 0; ci < C; ++ci) {
        const float* fb  = f_s  + ci*HS + base;
        const float* h0b = h0_s + ci*HS + base;
        const float* h1b = h1_s + ci*HS + base;
        const ulonglong2* wci = reinterpret_cast<const ulonglong2*>(wrel2 + ci*9*C*4);
        #pragma unroll
        for (int r = 0; r < 3; ++r) {
            const int ro = r*PITCH;
            float f0 = fb[ro],  f1 = fb[ro+1],  f2 = fb[ro+2],  f3 = fb[ro+3];
            float g0 = h0b[ro], g1 = h0b[ro+1], g2 = h0b[ro+2], g3 = h0b[ro+3];
            float e0 = h1b[ro], e1 = h1b[ro+1], e2 = h1b[ro+2], e3 = h1b[ro+3];
            ull fp[3] = { pack2(f0,f1), pack2(f1,f2), pack2(f2,f3) };
            ull p0[3] = { pack2(g0,g1), pack2(g1,g2), pack2(g2,g3) };
            ull p1[3] = { pack2(e0,e1), pack2(e1,e2), pack2(e2,e3) };
            #pragma unroll
            for (int kx = 0; kx < 3; ++kx) {
                const ulonglong2* wk = wci + (r*3 + kx)*C;
                ull fv = fp[kx], v0 = p0[kx], v1 = p1[kx];
                #pragma unroll
                for (int co = 0; co < C; ++co) {
                    ulonglong2 w = wk[co];
                    fma2(accf[co], w.x, fv);
                    fma2(acc0[co], w.y, v0);
                    fma2(acc1[co], w.y, v1);
                }
            }
        }
    }

    // ---- epilogue: BN bias + ReLU + sum -> packed comp_h / f center ----
    ull ch01[C], fc01[C];
    #pragma unroll
    for (int co = 0; co < C; ++co) {
        float cf0, cf1, x00, x01, x10, x11;
        unpack2(accf[co], cf0, cf1);
        unpack2(acc0[co], x00, x01);
        unpack2(acc1[co], x10, x11);
        float bz = b2_s[co];
        float c0 = fmaxf(cf0 + x00 + bz, 0.f) + fmaxf(cf0 + x10 + bz, 0.f);
        float c1 = fmaxf(cf1 + x01 + bz, 0.f) + fmaxf(cf1 + x11 + bz, 0.f);
        ch01[co] = pack2(c0, c1);
    }
    #pragma unroll
    for (int ci = 0; ci < C; ++ci) {
        const float* fc = f_s + ci*HS + (ty + 1)*PITCH + (txp + 1);
        fc01[ci] = pack2(fc[0], fc[1]);
    }

    // ---- ConvGRU gates (1x1), packed f32x2, weights from SMEM ----
    ull r01[C], u01[C];
    #pragma unroll
    for (int co = 0; co < C2; ++co) {
        float gb = gb_s[co];
        ull g = pack2(gb, gb);
        const ulonglong2* w = reinterpret_cast<const ulonglong2*>(wg2) + co*C;
        #pragma unroll
        for (int ci = 0; ci < C; ++ci) {
            ulonglong2 ww = w[ci];
            fma2(g, ww.x, ch01[ci]);
            fma2(g, ww.y, fc01[ci]);
        }
        float gg0, gg1; unpack2(g, gg0, gg1);
        ull s = pack2(fsigmoid(gg0), fsigmoid(gg1));
        if (co < C) r01[co] = s; else u01[co - C] = s;
    }
    ull rf01[C];
    #pragma unroll
    for (int ci = 0; ci < C; ++ci) rf01[ci] = mul2(r01[ci], fc01[ci]);

    // ---- candidate + update, write output ----
    const int gy = ty0 + ty, gx = tx0 + txp;
    #pragma unroll
    for (int co = 0; co < C; ++co) {
        float cb = cb_s[co];
        ull g = pack2(cb, cb);
        const ulonglong2* w = reinterpret_cast<const ulonglong2*>(wc2) + co*C;
        #pragma unroll
        for (int ci = 0; ci < C; ++ci) {
            ulonglong2 ww = w[ci];
            fma2(g, ww.x, ch01[ci]);
            fma2(g, ww.y, rf01[ci]);
        }
        float gg0, gg1; unpack2(g, gg0, gg1);
        float t0 = ftanh_fast(gg0), t1 = ftanh_fast(gg1);
        float fc0, fc1; unpack2(fc01[co], fc0, fc1);
        float u0, u1;  unpack2(u01[co], u0, u1);
        float r0 = fc0 + u0*(t0 - fc0);
        float r1 = fc1 + u1*(t1 - fc1);
        long o = ((long)(b*C + co)*HW + gy)*HW + gx;
        *reinterpret_cast<float2*>(out_f + o) = make_float2(r0, r1);
    }
}

extern "C" void kernel_launch(void* const* d_in, const int* in_sizes, int n_in,
                              void* d_out, int out_size) {
    (void)n_in; (void)out_size;
    const float* f_node   = (const float*)d_in[0];
    const float* h0       = (const float*)d_in[1];
    const float* h1       = (const float*)d_in[2];
    // d_in[3] = p_nodes (unused), d_in[4] = xf (unused)
    const float* att_w    = (const float*)d_in[5];
    const float* att_b    = (const float*)d_in[6];
    const float* rel_w    = (const float*)d_in[7];
    const float* bn_gamma = (const float*)d_in[8];
    const float* bn_beta  = (const float*)d_in[9];
    const float* bn_mean  = (const float*)d_in[10];
    const float* bn_var   = (const float*)d_in[11];
    const float* gates_w  = (const float*)d_in[12];
    const float* gates_b  = (const float*)d_in[13];
    const float* can_w    = (const float*)d_in[14];
    const float* can_b    = (const float*)d_in[15];

    int B = in_sizes[0] / (C * HW * HW);
    float* out_f   = (float*)d_out;
    float* out_att = out_f + (long)B * C * HW * HW;

    static bool attr_set = false;
    if (!attr_set) {
        cudaFuncSetAttribute(fused_tree_gru,
                             cudaFuncAttributeMaxDynamicSharedMemorySize, SMEM_BYTES);
        attr_set = true;
    }

    dim3 grid(HW / TW, HW / TH, B);
    fused_tree_gru<<<grid, NTHR, SMEM_BYTES>>>(f_node, h0, h1, att_w, att_b, rel_w,
                                               bn_gamma, bn_beta, bn_mean, bn_var,
                                               gates_w, gates_b, can_w, can_b,
                                               out_f, out_att);
}

// round 6
// speedup vs baseline: 1.5231x; 1.1052x over previous
#include <cuda_runtime.h>

#define C     10
#define C2    20
#define HW    128
#define TW    32
#define TH    16
#define PITCH 35            // odd pitch -> conflict-free half-warp offsets
#define HALOH 18
#define HS    (PITCH*HALOH) // 630 (even -> LDS.64 pairs stay aligned)
#define NTHR  256

typedef unsigned long long ull;

// shared layout (floats)
#define OFF_F     0
#define OFF_H0    (C*HS)                    // 6300
#define OFF_H1    (2*C*HS)                  // 12600
#define OFF_WREL  (3*C*HS)                  // 18900 (x4B = 75600, 16B aligned)
// wrel: per (ci*9+k)*5+cp : {wf(2cp), wf(2cp+1), wh(2cp), wh(2cp+1)}  -> 1800 floats
#define OFF_WG2   (OFF_WREL + C*9*C*2)      // 20700
#define OFF_WC2   (OFF_WG2 + C2*C*4)        // 21500
#define OFF_ATTW2 (OFF_WC2 + C*C*4)         // 21900  (20 dup pairs = 40 floats)
#define OFF_GB    (OFF_ATTW2 + C2*2)        // 21940
#define OFF_CB    (OFF_GB + C2)             // 21960
#define OFF_B2    (OFF_CB + C)              // 21970
#define OFF_ATTB  (OFF_B2 + C)              // 21980
#define SMEM_FLOATS (OFF_ATTB + 1)
#define SMEM_BYTES (SMEM_FLOATS*4)          // ~87.9 KB

__device__ __forceinline__ float fsigmoid(float x) { return 1.0f / (1.0f + __expf(-x)); }
__device__ __forceinline__ float ftanh_fast(float x) { return 1.0f - 2.0f / (__expf(2.0f * x) + 1.0f); }

__device__ __forceinline__ ull pack2(float lo, float hi) {
    ull r; asm("mov.b64 %0, {%1,%2};" : "=l"(r) : "f"(lo), "f"(hi)); return r;
}
__device__ __forceinline__ void unpack2(ull v, float& lo, float& hi) {
    asm("mov.b64 {%0,%1}, %2;" : "=f"(lo), "=f"(hi) : "l"(v));
}
__device__ __forceinline__ void fma2(ull& acc, ull a, ull b) {
    asm("fma.rn.f32x2 %0, %1, %2, %0;" : "+l"(acc) : "l"(a), "l"(b));
}
__device__ __forceinline__ ull mul2(ull a, ull b) {
    ull r; asm("mul.rn.f32x2 %0, %1, %2;" : "=l"(r) : "l"(a), "l"(b)); return r;
}

__global__ void __launch_bounds__(NTHR, 2)
fused_tree_gru(const float* __restrict__ f_node,
               const float* __restrict__ h0g,
               const float* __restrict__ h1g,
               const float* __restrict__ att_w,
               const float* __restrict__ att_b,
               const float* __restrict__ rel_w,
               const float* __restrict__ bn_gamma,
               const float* __restrict__ bn_beta,
               const float* __restrict__ bn_mean,
               const float* __restrict__ bn_var,
               const float* __restrict__ gates_w,
               const float* __restrict__ gates_b,
               const float* __restrict__ can_w,
               const float* __restrict__ can_b,
               float* __restrict__ out_f,
               float* __restrict__ out_att)
{
    extern __shared__ float sm[];
    float* f_s    = sm + OFF_F;
    float* h0_s   = sm + OFF_H0;
    float* h1_s   = sm + OFF_H1;
    float* wrel   = sm + OFF_WREL;
    float* wg2    = sm + OFF_WG2;    // {w1,w1,w2,w2} per co*10+ci, co in [0,20)
    float* wc2    = sm + OFF_WC2;    // {w1,w1,w2,w2} per co*10+ci, co in [0,10)
    float* attw2  = sm + OFF_ATTW2;  // {w,w} per ci in [0,20)
    float* gb_s   = sm + OFF_GB;
    float* cb_s   = sm + OFF_CB;
    float* b2_s   = sm + OFF_B2;
    float* attb_s = sm + OFF_ATTB;

    const int tid = threadIdx.x;
    const int b   = blockIdx.z;
    const int tx0 = blockIdx.x * TW;
    const int ty0 = blockIdx.y * TH;

    // ---- stage weights (folded, co-pair packed) ----
    // entry e = (ci*9 + k)*5 + cp : {wf(2cp), wf(2cp+1), wh(2cp), wh(2cp+1)}
    for (int e = tid; e < C*9*5; e += NTHR) {
        int cp = e % 5;
        int k  = (e / 5) % 9;
        int ci = e / 45;
        int coA = 2*cp, coB = 2*cp + 1;
        float invA = bn_gamma[coA] * rsqrtf(bn_var[coA] + 1e-5f);
        float invB = bn_gamma[coB] * rsqrtf(bn_var[coB] + 1e-5f);
        float* d = wrel + e*4;
        d[0] = rel_w[(coA*C2 + ci)*9 + k] * invA;
        d[1] = rel_w[(coB*C2 + ci)*9 + k] * invB;
        d[2] = rel_w[(coA*C2 + C + ci)*9 + k] * invA;
        d[3] = rel_w[(coB*C2 + C + ci)*9 + k] * invB;
    }
    for (int e = tid; e < C2*C; e += NTHR) {
        int co = e / C, ci = e % C;
        float w1 = gates_w[co*C2 + ci];
        float w2 = gates_w[co*C2 + C + ci];
        float* d = wg2 + e*4;
        d[0] = w1; d[1] = w1; d[2] = w2; d[3] = w2;
    }
    if (tid < C*C) {
        int co = tid / C, ci = tid % C;
        float w1 = can_w[co*C2 + ci];
        float w2 = can_w[co*C2 + C + ci];
        float* d = wc2 + tid*4;
        d[0] = w1; d[1] = w1; d[2] = w2; d[3] = w2;
    }
    if (tid < C2) {
        float aw = att_w[tid];
        attw2[tid*2] = aw; attw2[tid*2+1] = aw;
        gb_s[tid] = gates_b[tid];
    }
    if (tid < C) {
        cb_s[tid] = can_b[tid];
        float inv = bn_gamma[tid] * rsqrtf(bn_var[tid] + 1e-5f);
        b2_s[tid] = bn_beta[tid] - bn_mean[tid] * inv;
    }
    if (tid == 0) attb_s[0] = att_b[0];

    // ---- load haloed tiles: 18 slots/row (2 scalar edges + 16 aligned float2) ----
    for (int i = tid; i < 18*18; i += NTHR) {
        int ly = i / 18, slot = i - ly*18;
        int gy = ty0 - 1 + ly;
        bool okr = (gy >= 0) & (gy < HW);
        if (slot == 0 || slot == 17) {
            int lx = (slot == 0) ? 0 : 33;
            int gx = tx0 - 1 + lx;
            bool ok = okr & (gx >= 0) & (gx < HW);
            long gbase = ((long)(b*C)*HW + gy)*HW + gx;
            int  sbase = ly*PITCH + lx;
            #pragma unroll
            for (int ci = 0; ci < C; ++ci) {
                long gi = gbase + (long)ci*HW*HW;
                int  si = ci*HS + sbase;
                f_s [si] = ok ? f_node[gi] : 0.f;
                h0_s[si] = ok ? h0g[gi]    : 0.f;
                h1_s[si] = ok ? h1g[gi]    : 0.f;
            }
        } else {
            int lx = 2*slot - 1;             // 1,3,...,31
            int gx = tx0 - 1 + lx;           // even, always in [0,127]
            long gbase = ((long)(b*C)*HW + gy)*HW + gx;
            int  sbase = ly*PITCH + lx;
            #pragma unroll
            for (int ci = 0; ci < C; ++ci) {
                long gi = gbase + (long)ci*HW*HW;
                int  si = ci*HS + sbase;
                float2 vf = okr ? *reinterpret_cast<const float2*>(f_node + gi) : make_float2(0.f,0.f);
                float2 v0 = okr ? *reinterpret_cast<const float2*>(h0g + gi)    : make_float2(0.f,0.f);
                float2 v1 = okr ? *reinterpret_cast<const float2*>(h1g + gi)    : make_float2(0.f,0.f);
                f_s [si] = vf.x; f_s [si+1] = vf.y;
                h0_s[si] = v0.x; h0_s[si+1] = v0.y;
                h1_s[si] = v1.x; h1_s[si+1] = v1.y;
            }
        }
    }
    __syncthreads();

    // ---- attention (2 px/iter, f32x2): scale h tiles in place ----
    {
        float ab = attb_s[0];
        for (int q = tid; q < HS/2; q += NTHR) {
            int p2 = q*2;
            ull v0[C], v1[C];
            ull s = pack2(ab, ab);
            #pragma unroll
            for (int ci = 0; ci < C; ++ci) {
                v0[ci] = *reinterpret_cast<ull*>(h0_s + ci*HS + p2);
                v1[ci] = *reinterpret_cast<ull*>(h1_s + ci*HS + p2);
                fma2(s, reinterpret_cast<ull*>(attw2)[ci],   v0[ci]);
                fma2(s, reinterpret_cast<ull*>(attw2)[C+ci], v1[ci]);
            }
            float s0, s1; unpack2(s, s0, s1);
            float a0 = fsigmoid(s0), a1 = fsigmoid(s1);
            ull ap = pack2(a0, a1);
            #pragma unroll
            for (int ci = 0; ci < C; ++ci) {
                *reinterpret_cast<ull*>(h0_s + ci*HS + p2) = mul2(v0[ci], ap);
                *reinterpret_cast<ull*>(h1_s + ci*HS + p2) = mul2(v1[ci], ap);
            }
            int ly0 = p2 / PITCH, lx0 = p2 - ly0*PITCH;
            if (ly0 >= 1 && ly0 <= TH && lx0 >= 1 && lx0 <= TW)
                out_att[((long)b*HW + (ty0 + ly0 - 1))*HW + (tx0 + lx0 - 1)] = a0;
            int p3 = p2 + 1;
            int ly1 = p3 / PITCH, lx1 = p3 - ly1*PITCH;
            if (ly1 >= 1 && ly1 <= TH && lx1 >= 1 && lx1 <= TW)
                out_att[((long)b*HW + (ty0 + ly1 - 1))*HW + (tx0 + lx1 - 1)] = a1;
        }
    }
    __syncthreads();

    // ---- 3x3 conv: accumulators [co-pair][pixel], weights 1 LDS.128 per 6 fma2 ----
    const int txp  = (tid & 15) * 2;   // 0..30
    const int ty   = tid >> 4;         // 0..15
    const int base = ty*PITCH + txp;

    ull accf[5][2], acc0[5][2], acc1[5][2];
    #pragma unroll
    for (int cp = 0; cp < 5; ++cp) {
        accf[cp][0] = accf[cp][1] = 0ull;
        acc0[cp][0] = acc0[cp][1] = 0ull;
        acc1[cp][0] = acc1[cp][1] = 0ull;
    }

    for (int ci = 0; ci < C; ++ci) {
        const float* fb  = f_s  + ci*HS + base;
        const float* h0b = h0_s + ci*HS + base;
        const float* h1b = h1_s + ci*HS + base;
        const ulonglong2* wci = reinterpret_cast<const ulonglong2*>(wrel + ci*9*5*4);
        #pragma unroll
        for (int r = 0; r < 3; ++r) {
            const int ro = r*PITCH;
            ull fd[4], gd[4], ed[4];
            #pragma unroll
            for (int t = 0; t < 4; ++t) {
                float fv = fb[ro+t], gv = h0b[ro+t], ev = h1b[ro+t];
                fd[t] = pack2(fv, fv);
                gd[t] = pack2(gv, gv);
                ed[t] = pack2(ev, ev);
            }
            #pragma unroll
            for (int kx = 0; kx < 3; ++kx) {
                const ulonglong2* wk = wci + (r*3 + kx)*5;
                #pragma unroll
                for (int cp = 0; cp < 5; ++cp) {
                    ulonglong2 w = wk[cp];   // .x={wfA,wfB} .y={whA,whB}
                    fma2(accf[cp][0], w.x, fd[kx]);
                    fma2(accf[cp][1], w.x, fd[kx+1]);
                    fma2(acc0[cp][0], w.y, gd[kx]);
                    fma2(acc0[cp][1], w.y, gd[kx+1]);
                    fma2(acc1[cp][0], w.y, ed[kx]);
                    fma2(acc1[cp][1], w.y, ed[kx+1]);
                }
            }
        }
    }

    // ---- epilogue: BN bias + ReLU + sum -> packed comp_h / f center ----
    ull ch01[C], fc01[C];
    #pragma unroll
    for (int cp = 0; cp < 5; ++cp) {
        float chv[2][2];
        #pragma unroll
        for (int px = 0; px < 2; ++px) {
            float afA, afB, x0A, x0B, x1A, x1B;
            unpack2(accf[cp][px], afA, afB);
            unpack2(acc0[cp][px], x0A, x0B);
            unpack2(acc1[cp][px], x1A, x1B);
            float bzA = b2_s[2*cp], bzB = b2_s[2*cp+1];
            chv[px][0] = fmaxf(afA + x0A + bzA, 0.f) + fmaxf(afA + x1A + bzA, 0.f);
            chv[px][1] = fmaxf(afB + x0B + bzB, 0.f) + fmaxf(afB + x1B + bzB, 0.f);
        }
        ch01[2*cp]   = pack2(chv[0][0], chv[1][0]);
        ch01[2*cp+1] = pack2(chv[0][1], chv[1][1]);
    }
    #pragma unroll
    for (int ci = 0; ci < C; ++ci) {
        const float* fc = f_s + ci*HS + (ty + 1)*PITCH + (txp + 1);
        fc01[ci] = pack2(fc[0], fc[1]);
    }

    // ---- ConvGRU gates (1x1), packed f32x2, weights from SMEM ----
    ull r01[C], u01[C];
    #pragma unroll
    for (int co = 0; co < C2; ++co) {
        float gb = gb_s[co];
        ull g = pack2(gb, gb);
        const ulonglong2* w = reinterpret_cast<const ulonglong2*>(wg2) + co*C;
        #pragma unroll
        for (int ci = 0; ci < C; ++ci) {
            ulonglong2 ww = w[ci];
            fma2(g, ww.x, ch01[ci]);
            fma2(g, ww.y, fc01[ci]);
        }
        float gg0, gg1; unpack2(g, gg0, gg1);
        ull s = pack2(fsigmoid(gg0), fsigmoid(gg1));
        if (co < C) r01[co] = s; else u01[co - C] = s;
    }
    ull rf01[C];
    #pragma unroll
    for (int ci = 0; ci < C; ++ci) rf01[ci] = mul2(r01[ci], fc01[ci]);

    // ---- candidate + update, write output ----
    const int gy = ty0 + ty, gx = tx0 + txp;
    #pragma unroll
    for (int co = 0; co < C; ++co) {
        float cb = cb_s[co];
        ull g = pack2(cb, cb);
        const ulonglong2* w = reinterpret_cast<const ulonglong2*>(wc2) + co*C;
        #pragma unroll
        for (int ci = 0; ci < C; ++ci) {
            ulonglong2 ww = w[ci];
            fma2(g, ww.x, ch01[ci]);
            fma2(g, ww.y, rf01[ci]);
        }
        float gg0, gg1; unpack2(g, gg0, gg1);
        float t0 = ftanh_fast(gg0), t1 = ftanh_fast(gg1);
        float fc0, fc1; unpack2(fc01[co], fc0, fc1);
        float u0, u1;  unpack2(u01[co], u0, u1);
        float r0 = fc0 + u0*(t0 - fc0);
        float r1 = fc1 + u1*(t1 - fc1);
        long o = ((long)(b*C + co)*HW + gy)*HW + gx;
        *reinterpret_cast<float2*>(out_f + o) = make_float2(r0, r1);
    }
}

extern "C" void kernel_launch(void* const* d_in, const int* in_sizes, int n_in,
                              void* d_out, int out_size) {
    (void)n_in; (void)out_size;
    const float* f_node   = (const float*)d_in[0];
    const float* h0       = (const float*)d_in[1];
    const float* h1       = (const float*)d_in[2];
    // d_in[3] = p_nodes (unused), d_in[4] = xf (unused)
    const float* att_w    = (const float*)d_in[5];
    const float* att_b    = (const float*)d_in[6];
    const float* rel_w    = (const float*)d_in[7];
    const float* bn_gamma = (const float*)d_in[8];
    const float* bn_beta  = (const float*)d_in[9];
    const float* bn_mean  = (const float*)d_in[10];
    const float* bn_var   = (const float*)d_in[11];
    const float* gates_w  = (const float*)d_in[12];
    const float* gates_b  = (const float*)d_in[13];
    const float* can_w    = (const float*)d_in[14];
    const float* can_b    = (const float*)d_in[15];

    int B = in_sizes[0] / (C * HW * HW);
    float* out_f   = (float*)d_out;
    float* out_att = out_f + (long)B * C * HW * HW;

    static bool attr_set = false;
    if (!attr_set) {
        cudaFuncSetAttribute(fused_tree_gru,
                             cudaFuncAttributeMaxDynamicSharedMemorySize, SMEM_BYTES);
        attr_set = true;
    }

    dim3 grid(HW / TW, HW / TH, B);
    fused_tree_gru<<<grid, NTHR, SMEM_BYTES>>>(f_node, h0, h1, att_w, att_b, rel_w,
                                               bn_gamma, bn_beta, bn_mean, bn_var,
                                               gates_w, gates_b, can_w, can_b,
                                               out_f, out_att);
}